// round 7
// baseline (speedup 1.0000x reference)
#include <cuda_runtime.h>
#include <cuda_bf16.h>
#include <cstdint>

#define N_NODES 100000
#define N_EDGES 3200000
#define NF      128
#define H1      32
#define H2      16
#define NG      64

// ---------------- scratch (static device globals; no allocation) -------------
__device__ float4 g_y1_4  [N_NODES * H1 / 4];   // (x@W1)*dis[src], 12.8 MB
__device__ float4 g_acc1_4[N_NODES * H1 / 4];   // edge-summed y1,   12.8 MB
__device__ float4 g_y2_4  [N_NODES * H2 / 4];   // layer2 premult,    6.4 MB
__device__ float4 g_acc2_4[N_NODES * H2 / 4];   //                    6.4 MB
__device__ float  g_dis   [N_NODES];            // deg -> rsqrt(deg) in place
__device__ int    g_src32 [N_EDGES];
__device__ int    g_dst32 [N_EDGES];
__device__ float  g_gsum  [NG];
__device__ float  g_gcnt  [NG];

__device__ __forceinline__ void red_add_v4(float* addr, float4 v) {
    asm volatile("red.global.add.v4.f32 [%0], {%1,%2,%3,%4};"
                 :: "l"(addr), "f"(v.x), "f"(v.y), "f"(v.z), "f"(v.w)
                 : "memory");
}

__device__ __forceinline__ int clampi(int v, int hi) {   // [0, hi)
    return v < 0 ? 0 : (v >= hi ? hi - 1 : v);
}

// ---------------- kernels ---------------------------------------------------

// Zero accumulators, deg=1 (self loop), graph sums. 800000 threads exactly.
__global__ void k_init() {
    int i = blockIdx.x * 256 + threadIdx.x;          // 0 .. 799999
    float4 z = make_float4(0.f, 0.f, 0.f, 0.f);
    g_acc1_4[i] = z;                                  // 800000 float4
    if (i < N_NODES * H2 / 4) g_acc2_4[i] = z;        // 400000 float4
    if (i < N_NODES)          g_dis[i] = 1.0f;        // deg starts at 1 (self loop)
    if (i < NG) { g_gsum[i] = 0.f; g_gcnt[i] = 0.f; }
}

// edge_index is INT32 (JAX x64 disabled). Copy clamped; accumulate in-degree.
__global__ void k_deg(const int* __restrict__ ei) {
    int e = blockIdx.x * 256 + threadIdx.x;
    if (e >= N_EDGES) return;
    int s = clampi(ei[e], N_NODES);
    int d = clampi(ei[N_EDGES + e], N_NODES);
    g_src32[e] = s;
    g_dst32[e] = d;
    atomicAdd(&g_dis[d], 1.0f);
}

__global__ void k_rsqrt() {
    int i = blockIdx.x * 256 + threadIdx.x;
    if (i < N_NODES) g_dis[i] = rsqrtf(g_dis[i]);    // deg >= 1 always
}

// y1[node] = (x[node] @ W1) * dis[node].  8 nodes per 256-thread block.
__global__ void k_xw1(const float* __restrict__ x, const float* __restrict__ W1) {
    __shared__ float W1s[NF * H1];     // 16 KB
    __shared__ float rows[8][NF];      //  4 KB
    int tid = threadIdx.x;
    for (int i = tid; i < NF * H1; i += 256) W1s[i] = W1[i];
    __syncthreads();
    int grp  = tid >> 5, lane = tid & 31;
    int node = blockIdx.x * 8 + grp;
    if (node >= N_NODES) return;
    const float* xr = x + (size_t)node * NF;
    for (int c = lane; c < NF; c += 32) rows[grp][c] = xr[c];
    __syncwarp();
    float acc = 0.f;
    #pragma unroll
    for (int k = 0; k < NF; k++)
        acc = fmaf(rows[grp][k], W1s[k * H1 + lane], acc);
    float* y1 = (float*)g_y1_4;
    y1[(size_t)node * H1 + lane] = acc * g_dis[node];
}

// Edge scatter, layer 1: acc1[dst] += y1[src].  (edge, chunk) per thread,
// 8 float4 chunks per edge; 8 consecutive threads -> same row, coalesced.
__global__ void k_scatter1() {
    int idx = blockIdx.x * 256 + threadIdx.x;        // < N_EDGES*8 = 25.6M
    if (idx >= N_EDGES * 8) return;
    int e = idx >> 3, c = idx & 7;
    int s = g_src32[e], d = g_dst32[e];
    float4 v = g_y1_4[s * 8 + c];
    red_add_v4((float*)&g_acc1_4[d * 8 + c], v);
}

// h = relu(dis*(acc1+y1) + b1);  y2 = (h @ W2) * dis.   One node per thread.
__global__ void k_layer2(const float* __restrict__ b1, const float* __restrict__ W2) {
    __shared__ float W2s[H1 * H2];   // 2 KB
    __shared__ float b1s[H1];
    int tid = threadIdx.x;
    for (int i = tid; i < H1 * H2; i += 256) W2s[i] = W2[i];
    if (tid < H1) b1s[tid] = b1[tid];
    __syncthreads();
    int node = blockIdx.x * 256 + tid;
    if (node >= N_NODES) return;
    float dis = g_dis[node];
    float h[H1];
    #pragma unroll
    for (int q = 0; q < 8; q++) {
        float4 a = g_acc1_4[node * 8 + q];
        float4 y = g_y1_4 [node * 8 + q];
        h[q*4+0] = fmaxf(fmaf(dis, a.x + y.x, b1s[q*4+0]), 0.f);
        h[q*4+1] = fmaxf(fmaf(dis, a.y + y.y, b1s[q*4+1]), 0.f);
        h[q*4+2] = fmaxf(fmaf(dis, a.z + y.z, b1s[q*4+2]), 0.f);
        h[q*4+3] = fmaxf(fmaf(dis, a.w + y.w, b1s[q*4+3]), 0.f);
    }
    float o[H2];
    #pragma unroll
    for (int j = 0; j < H2; j++) o[j] = 0.f;
    #pragma unroll
    for (int k = 0; k < H1; k++) {
        float hk = h[k];
        #pragma unroll
        for (int j = 0; j < H2; j++)
            o[j] = fmaf(hk, W2s[k * H2 + j], o[j]);
    }
    #pragma unroll
    for (int q = 0; q < 4; q++)
        g_y2_4[node * 4 + q] = make_float4(o[q*4+0]*dis, o[q*4+1]*dis,
                                           o[q*4+2]*dis, o[q*4+3]*dis);
}

// Edge scatter, layer 2: acc2[dst] += y2[src].  4 chunks per edge.
__global__ void k_scatter2() {
    int idx = blockIdx.x * 256 + threadIdx.x;        // < N_EDGES*4 = 12.8M
    if (idx >= N_EDGES * 4) return;
    int e = idx >> 2, c = idx & 3;
    int s = g_src32[e], d = g_dst32[e];
    float4 v = g_y2_4[s * 4 + c];
    red_add_v4((float*)&g_acc2_4[d * 4 + c], v);
}

// s_i = (dis*(acc2+y2) + b2) . lin_w ; warp-aggregated per-graph reduction.
// batch is INT32.
__global__ void k_pool(const int* __restrict__ batch,
                       const float* __restrict__ b2,
                       const float* __restrict__ lw) {
    int i = blockIdx.x * 256 + threadIdx.x;
    bool act = (i < N_NODES);
    float s = 0.f;
    int g = 0;
    if (act) {
        float dis = g_dis[i];
        #pragma unroll
        for (int q = 0; q < 4; q++) {
            float4 a = g_acc2_4[i * 4 + q];
            float4 y = g_y2_4 [i * 4 + q];
            s = fmaf(fmaf(dis, a.x + y.x, b2[q*4+0]), lw[q*4+0], s);
            s = fmaf(fmaf(dis, a.y + y.y, b2[q*4+1]), lw[q*4+1], s);
            s = fmaf(fmaf(dis, a.z + y.z, b2[q*4+2]), lw[q*4+2], s);
            s = fmaf(fmaf(dis, a.w + y.w, b2[q*4+3]), lw[q*4+3], s);
        }
        g = clampi(batch[i], NG);
    }
    unsigned mask = __ballot_sync(0xffffffffu, act);
    if (!act) return;
    // batch is sorted: most full warps see a single graph id.
    if (mask == 0xffffffffu && __all_sync(0xffffffffu, g == __shfl_sync(0xffffffffu, g, 0))) {
        #pragma unroll
        for (int o = 16; o > 0; o >>= 1) s += __shfl_down_sync(0xffffffffu, s, o);
        if ((threadIdx.x & 31) == 0) {
            atomicAdd(&g_gsum[g], s);
            atomicAdd(&g_gcnt[g], 32.f);
        }
    } else {
        atomicAdd(&g_gsum[g], s);
        atomicAdd(&g_gcnt[g], 1.f);
    }
}

__global__ void k_final(const float* __restrict__ lb, float* __restrict__ out) {
    int g = threadIdx.x;
    if (g < NG) out[g] = g_gsum[g] / fmaxf(g_gcnt[g], 1.f) + lb[0];
}

// ---------------- launch -----------------------------------------------------
// Inputs are bound BY ELEMENT COUNT, not by position, so any metadata ordering
// works. Sizes: x=12.8M, edge_index=6.4M, batch=100000, W1=4096, b1=32,
// W2=512, b2=16 (first), lin_w=16 (second), lin_b=1.  b2 precedes lin_w in
// both insertion order and alphabetical order.
extern "C" void kernel_launch(void* const* d_in, const int* in_sizes, int n_in,
                              void* d_out, int out_size) {
    const void* p_by_size[9] = {0,0,0,0,0,0,0,0,0};
    int sixteen_seen = 0;
    const void *p16a = 0, *p16b = 0;
    for (int i = 0; i < n_in; i++) {
        switch (in_sizes[i]) {
            case N_NODES * NF:   p_by_size[0] = d_in[i]; break;  // x
            case 2 * N_EDGES:    p_by_size[1] = d_in[i]; break;  // edge_index
            case N_NODES:        p_by_size[2] = d_in[i]; break;  // batch
            case NF * H1:        p_by_size[3] = d_in[i]; break;  // W1
            case H1:             p_by_size[4] = d_in[i]; break;  // b1
            case H1 * H2:        p_by_size[5] = d_in[i]; break;  // W2
            case H2:             if (sixteen_seen++ == 0) p16a = d_in[i];
                                 else                     p16b = d_in[i];
                                 break;                           // b2 then lin_w
            case 1:              p_by_size[8] = d_in[i]; break;  // lin_b
            default: break;
        }
    }
    p_by_size[6] = p16a;   // b2
    p_by_size[7] = p16b;   // lin_w
    // fallback to positional if anything failed to bind
    for (int i = 0; i < 9; i++) if (!p_by_size[i] && i < n_in) p_by_size[i] = d_in[i];

    const float* x     = (const float*)p_by_size[0];
    const int*   ei    = (const int*)p_by_size[1];
    const int*   batch = (const int*)p_by_size[2];
    const float* W1    = (const float*)p_by_size[3];
    const float* b1    = (const float*)p_by_size[4];
    const float* W2    = (const float*)p_by_size[5];
    const float* b2    = (const float*)p_by_size[6];
    const float* lw    = (const float*)p_by_size[7];
    const float* lb    = (const float*)p_by_size[8];
    float*       out   = (float*)d_out;

    k_init    <<<(N_NODES * H1 / 4 + 255) / 256, 256>>>();
    k_deg     <<<(N_EDGES + 255) / 256, 256>>>(ei);
    k_rsqrt   <<<(N_NODES + 255) / 256, 256>>>();
    k_xw1     <<<(N_NODES + 7) / 8, 256>>>(x, W1);
    k_scatter1<<<(N_EDGES * 8 + 255) / 256, 256>>>();
    k_layer2  <<<(N_NODES + 255) / 256, 256>>>(b1, W2);
    k_scatter2<<<(N_EDGES * 4 + 255) / 256, 256>>>();
    k_pool    <<<(N_NODES + 255) / 256, 256>>>(batch, b2, lw);
    k_final   <<<1, 64>>>(lb, out);
}

// round 8
// speedup vs baseline: 1.1996x; 1.1996x over previous
#include <cuda_runtime.h>
#include <cuda_bf16.h>
#include <cstdint>

#define N_NODES 100000
#define N_EDGES 3200000
#define NF      128
#define H1      32
#define H2      16
#define NG      64
#define TN      64          // nodes per k_xw1 block

// ---------------- scratch (static device globals; no allocation) -------------
__device__ float4 g_y1_4  [N_NODES * H1 / 4];   // (x@W1)*dis[src], 12.8 MB
__device__ float4 g_acc1_4[N_NODES * H1 / 4];   // edge-summed y1,   12.8 MB
__device__ float4 g_y2_4  [N_NODES * H2 / 4];   // layer2 premult,    6.4 MB
__device__ float4 g_acc2_4[N_NODES * H2 / 4];   //                    6.4 MB
__device__ float  g_dis   [N_NODES];            // deg -> rsqrt(deg) in place
__device__ int    g_src32 [N_EDGES];
__device__ int    g_dst32 [N_EDGES];
__device__ float  g_gsum  [NG];
__device__ float  g_gcnt  [NG];

__device__ __forceinline__ void red_add_v4(float* addr, float4 v) {
    asm volatile("red.global.add.v4.f32 [%0], {%1,%2,%3,%4};"
                 :: "l"(addr), "f"(v.x), "f"(v.y), "f"(v.z), "f"(v.w)
                 : "memory");
}

__device__ __forceinline__ int clampi(int v, int hi) {   // [0, hi)
    return v < 0 ? 0 : (v >= hi ? hi - 1 : v);
}

// ---------------- kernels ---------------------------------------------------

// Zero accumulators, deg=1 (self loop), graph sums. 800000 threads exactly.
__global__ void k_init() {
    int i = blockIdx.x * 256 + threadIdx.x;          // 0 .. 799999
    float4 z = make_float4(0.f, 0.f, 0.f, 0.f);
    g_acc1_4[i] = z;                                  // 800000 float4
    if (i < N_NODES * H2 / 4) g_acc2_4[i] = z;        // 400000 float4
    if (i < N_NODES)          g_dis[i] = 1.0f;        // deg starts at 1 (self loop)
    if (i < NG) { g_gsum[i] = 0.f; g_gcnt[i] = 0.f; }
}

// edge_index is INT32. Copy clamped; accumulate in-degree.
__global__ void k_deg(const int* __restrict__ ei) {
    int e = blockIdx.x * 256 + threadIdx.x;
    if (e >= N_EDGES) return;
    int s = clampi(ei[e], N_NODES);
    int d = clampi(ei[N_EDGES + e], N_NODES);
    g_src32[e] = s;
    g_dst32[e] = d;
    atomicAdd(&g_dis[d], 1.0f);
}

__global__ void k_rsqrt() {
    int i = blockIdx.x * 256 + threadIdx.x;
    if (i < N_NODES) g_dis[i] = rsqrtf(g_dis[i]);    // deg >= 1 always
}

// y1[node] = (x[node] @ W1) * dis[node].
// Register-tiled: block = 64 nodes x 32 cols; thread = 8 nodes x 1 col.
// Per float4 k-chunk: 4 conflict-free W1 LDS + 8 broadcast LDS.128 + 32 FFMA.
__global__ __launch_bounds__(256) void k_xw1(const float* __restrict__ x,
                                             const float* __restrict__ W1) {
    __shared__ float  W1s[NF * H1];          // 16 KB
    __shared__ float4 rows4[TN][NF / 4];     // 32 KB
    int tid  = threadIdx.x;
    int base = blockIdx.x * TN;

    // stage W1 (vectorized, coalesced)
    for (int i = tid; i < NF * H1 / 4; i += 256)
        ((float4*)W1s)[i] = ((const float4*)W1)[i];

    // stage 64 node rows (coalesced float4; clamp for the partial last block)
    for (int i = tid; i < TN * NF / 4; i += 256) {
        int node = i >> 5;                   // i / 32
        int c4   = i & 31;
        int gn   = base + node;
        if (gn >= N_NODES) gn = N_NODES - 1;
        ((float4*)rows4)[i] = ((const float4*)(x + (size_t)gn * NF))[c4];
    }
    __syncthreads();

    int ty   = tid >> 5;       // 0..7 : group of 8 nodes
    int lane = tid & 31;       // output column

    float acc[8];
    #pragma unroll
    for (int j = 0; j < 8; j++) acc[j] = 0.f;

    #pragma unroll 8
    for (int kk = 0; kk < NF / 4; kk++) {
        int k = kk * 4;
        float w0 = W1s[(k + 0) * H1 + lane];
        float w1 = W1s[(k + 1) * H1 + lane];
        float w2 = W1s[(k + 2) * H1 + lane];
        float w3 = W1s[(k + 3) * H1 + lane];
        #pragma unroll
        for (int j = 0; j < 8; j++) {
            float4 r = rows4[ty * 8 + j][kk];      // broadcast across warp
            acc[j] = fmaf(r.x, w0, acc[j]);
            acc[j] = fmaf(r.y, w1, acc[j]);
            acc[j] = fmaf(r.z, w2, acc[j]);
            acc[j] = fmaf(r.w, w3, acc[j]);
        }
    }

    float* y1 = (float*)g_y1_4;
    #pragma unroll
    for (int j = 0; j < 8; j++) {
        int gn = base + ty * 8 + j;
        if (gn < N_NODES)
            y1[(size_t)gn * H1 + lane] = acc[j] * g_dis[gn];
    }
}

// Edge scatter, layer 1: acc1[dst] += y1[src].  (edge, chunk) per thread,
// 8 float4 chunks per edge; 8 consecutive threads -> same row, coalesced.
__global__ void k_scatter1() {
    int idx = blockIdx.x * 256 + threadIdx.x;        // < N_EDGES*8 = 25.6M
    if (idx >= N_EDGES * 8) return;
    int e = idx >> 3, c = idx & 7;
    int s = g_src32[e], d = g_dst32[e];
    float4 v = g_y1_4[s * 8 + c];
    red_add_v4((float*)&g_acc1_4[d * 8 + c], v);
}

// h = relu(dis*(acc1+y1) + b1);  y2 = (h @ W2) * dis.   One node per thread.
__global__ void k_layer2(const float* __restrict__ b1, const float* __restrict__ W2) {
    __shared__ float W2s[H1 * H2];   // 2 KB
    __shared__ float b1s[H1];
    int tid = threadIdx.x;
    for (int i = tid; i < H1 * H2; i += 256) W2s[i] = W2[i];
    if (tid < H1) b1s[tid] = b1[tid];
    __syncthreads();
    int node = blockIdx.x * 256 + tid;
    if (node >= N_NODES) return;
    float dis = g_dis[node];
    float h[H1];
    #pragma unroll
    for (int q = 0; q < 8; q++) {
        float4 a = g_acc1_4[node * 8 + q];
        float4 y = g_y1_4 [node * 8 + q];
        h[q*4+0] = fmaxf(fmaf(dis, a.x + y.x, b1s[q*4+0]), 0.f);
        h[q*4+1] = fmaxf(fmaf(dis, a.y + y.y, b1s[q*4+1]), 0.f);
        h[q*4+2] = fmaxf(fmaf(dis, a.z + y.z, b1s[q*4+2]), 0.f);
        h[q*4+3] = fmaxf(fmaf(dis, a.w + y.w, b1s[q*4+3]), 0.f);
    }
    float o[H2];
    #pragma unroll
    for (int j = 0; j < H2; j++) o[j] = 0.f;
    #pragma unroll
    for (int k = 0; k < H1; k++) {
        float hk = h[k];
        #pragma unroll
        for (int j = 0; j < H2; j++)
            o[j] = fmaf(hk, W2s[k * H2 + j], o[j]);
    }
    #pragma unroll
    for (int q = 0; q < 4; q++)
        g_y2_4[node * 4 + q] = make_float4(o[q*4+0]*dis, o[q*4+1]*dis,
                                           o[q*4+2]*dis, o[q*4+3]*dis);
}

// Edge scatter, layer 2: acc2[dst] += y2[src].  4 chunks per edge.
__global__ void k_scatter2() {
    int idx = blockIdx.x * 256 + threadIdx.x;        // < N_EDGES*4 = 12.8M
    if (idx >= N_EDGES * 4) return;
    int e = idx >> 2, c = idx & 3;
    int s = g_src32[e], d = g_dst32[e];
    float4 v = g_y2_4[s * 4 + c];
    red_add_v4((float*)&g_acc2_4[d * 4 + c], v);
}

// s_i = (dis*(acc2+y2) + b2) . lin_w ; warp-aggregated per-graph reduction.
__global__ void k_pool(const int* __restrict__ batch,
                       const float* __restrict__ b2,
                       const float* __restrict__ lw) {
    int i = blockIdx.x * 256 + threadIdx.x;
    bool act = (i < N_NODES);
    float s = 0.f;
    int g = 0;
    if (act) {
        float dis = g_dis[i];
        #pragma unroll
        for (int q = 0; q < 4; q++) {
            float4 a = g_acc2_4[i * 4 + q];
            float4 y = g_y2_4 [i * 4 + q];
            s = fmaf(fmaf(dis, a.x + y.x, b2[q*4+0]), lw[q*4+0], s);
            s = fmaf(fmaf(dis, a.y + y.y, b2[q*4+1]), lw[q*4+1], s);
            s = fmaf(fmaf(dis, a.z + y.z, b2[q*4+2]), lw[q*4+2], s);
            s = fmaf(fmaf(dis, a.w + y.w, b2[q*4+3]), lw[q*4+3], s);
        }
        g = clampi(batch[i], NG);
    }
    unsigned mask = __ballot_sync(0xffffffffu, act);
    if (!act) return;
    // batch is sorted: most full warps see a single graph id.
    if (mask == 0xffffffffu && __all_sync(0xffffffffu, g == __shfl_sync(0xffffffffu, g, 0))) {
        #pragma unroll
        for (int o = 16; o > 0; o >>= 1) s += __shfl_down_sync(0xffffffffu, s, o);
        if ((threadIdx.x & 31) == 0) {
            atomicAdd(&g_gsum[g], s);
            atomicAdd(&g_gcnt[g], 32.f);
        }
    } else {
        atomicAdd(&g_gsum[g], s);
        atomicAdd(&g_gcnt[g], 1.f);
    }
}

__global__ void k_final(const float* __restrict__ lb, float* __restrict__ out) {
    int g = threadIdx.x;
    if (g < NG) out[g] = g_gsum[g] / fmaxf(g_gcnt[g], 1.f) + lb[0];
}

// ---------------- launch -----------------------------------------------------
extern "C" void kernel_launch(void* const* d_in, const int* in_sizes, int n_in,
                              void* d_out, int out_size) {
    const void* p_by_size[9] = {0,0,0,0,0,0,0,0,0};
    int sixteen_seen = 0;
    const void *p16a = 0, *p16b = 0;
    for (int i = 0; i < n_in; i++) {
        switch (in_sizes[i]) {
            case N_NODES * NF:   p_by_size[0] = d_in[i]; break;  // x
            case 2 * N_EDGES:    p_by_size[1] = d_in[i]; break;  // edge_index
            case N_NODES:        p_by_size[2] = d_in[i]; break;  // batch
            case NF * H1:        p_by_size[3] = d_in[i]; break;  // W1
            case H1:             p_by_size[4] = d_in[i]; break;  // b1
            case H1 * H2:        p_by_size[5] = d_in[i]; break;  // W2
            case H2:             if (sixteen_seen++ == 0) p16a = d_in[i];
                                 else                     p16b = d_in[i];
                                 break;                           // b2 then lin_w
            case 1:              p_by_size[8] = d_in[i]; break;  // lin_b
            default: break;
        }
    }
    p_by_size[6] = p16a;   // b2
    p_by_size[7] = p16b;   // lin_w
    for (int i = 0; i < 9; i++) if (!p_by_size[i] && i < n_in) p_by_size[i] = d_in[i];

    const float* x     = (const float*)p_by_size[0];
    const int*   ei    = (const int*)p_by_size[1];
    const int*   batch = (const int*)p_by_size[2];
    const float* W1    = (const float*)p_by_size[3];
    const float* b1    = (const float*)p_by_size[4];
    const float* W2    = (const float*)p_by_size[5];
    const float* b2    = (const float*)p_by_size[6];
    const float* lw    = (const float*)p_by_size[7];
    const float* lb    = (const float*)p_by_size[8];
    float*       out   = (float*)d_out;

    k_init    <<<(N_NODES * H1 / 4 + 255) / 256, 256>>>();
    k_deg     <<<(N_EDGES + 255) / 256, 256>>>(ei);
    k_rsqrt   <<<(N_NODES + 255) / 256, 256>>>();
    k_xw1     <<<(N_NODES + TN - 1) / TN, 256>>>(x, W1);
    k_scatter1<<<(N_EDGES * 8 + 255) / 256, 256>>>();
    k_layer2  <<<(N_NODES + 255) / 256, 256>>>(b1, W2);
    k_scatter2<<<(N_EDGES * 4 + 255) / 256, 256>>>();
    k_pool    <<<(N_NODES + 255) / 256, 256>>>(batch, b2, lw);
    k_final   <<<1, 64>>>(lb, out);
}